// round 4
// baseline (speedup 1.0000x reference)
#include <cuda_runtime.h>
#include <cstdint>

// VDPDropout fused single-kernel:
//   mu_out    = keep ? mu*1.25 : 0                       [B, H]
//   Sigma_out = 1.5625 * Sigma * (nz_i & nz_j)           [B, H, H]
// Dropped rows are written as zeros WITHOUT reading Sigma_in. The hot loop is
// branch-free (compacted row lists) so loads batch for MLP=4.

#define B 32
#define H 2048
#define BH (B * H)              // 65536
#define RPB 16                  // rows per block; 16 | 2048 -> no batch straddle
#define GRID (BH / RPB)         // 4096

__global__ void __launch_bounds__(512)
fused_kernel(const float* __restrict__ mu,
             const unsigned int* __restrict__ mask,
             float* __restrict__ mu_out,
             const float4* __restrict__ Sin,
             float4* __restrict__ Sout) {
    int r0 = blockIdx.x * RPB;          // first row this block owns
    int b  = r0 >> 11;                  // batch index
    __shared__ unsigned char snz[H];
    __shared__ short keeplist[RPB], droplist[RPB];
    __shared__ int nk, nd;

    // ---- mask dtype detection (identical in every block; L2 broadcast) ----
    unsigned int w = (threadIdx.x < 256) ? mask[threadIdx.x] : 0u;
    int bad_i = (threadIdx.x < 256) && (w > 1u);
    int bad_f = (threadIdx.x < 256) && (w != 0u) && (w != 0x3F800000u);
    int any_bad_i = __syncthreads_or(bad_i);
    int any_bad_f = __syncthreads_or(bad_f);
    int kind = !any_bad_i ? 0 : (!any_bad_f ? 1 : 2);

    // ---- recompute this batch's nz row from mu+mask (L2-resident) ----
    int t = threadIdx.x;                // 0..511, 4 elems each = 2048
    float4 mo;
    unsigned char n0, n1, n2, n3;
    {
        float vq[4];
#pragma unroll
        for (int q = 0; q < 4; q++) {
            int gi = b * H + (t << 2) + q;
            bool keep;
            if (kind == 0)      keep = ((const int*)mask)[gi] != 0;
            else if (kind == 1) keep = ((const float*)mask)[gi] != 0.0f;
            else                keep = ((const unsigned char*)mask)[gi] != 0;
            vq[q] = keep ? mu[gi] * 1.25f : 0.0f;
        }
        mo.x = vq[0]; mo.y = vq[1]; mo.z = vq[2]; mo.w = vq[3];
        n0 = vq[0] != 0.0f; n1 = vq[1] != 0.0f;
        n2 = vq[2] != 0.0f; n3 = vq[3] != 0.0f;
    }
    *reinterpret_cast<uchar4*>(snz + (t << 2)) = make_uchar4(n0, n1, n2, n3);

    // one block per batch (the one owning rows [0,16)) also writes mu_out
    if ((r0 & (H - 1)) == 0)
        reinterpret_cast<float4*>(mu_out)[b * (H / 4) + t] = mo;
    __syncthreads();

    // ---- compact this block's rows into kept / dropped lists ----
    if (t == 0) {
        int k = 0, d = 0;
        for (int rr = 0; rr < RPB; rr++) {
            if (snz[(r0 + rr) & (H - 1)]) keeplist[k++] = (short)rr;
            else                          droplist[d++] = (short)rr;
        }
        nk = k; nd = d;
    }
    __syncthreads();

    int j = t << 2;
    bool c0 = snz[j + 0], c1 = snz[j + 1], c2 = snz[j + 2], c3 = snz[j + 3];

    const float4* src = Sin + (size_t)r0 * (H / 4) + t;
    float4*       dst = Sout + (size_t)r0 * (H / 4) + t;
    const float4 zero4 = make_float4(0.f, 0.f, 0.f, 0.f);
    int NK = nk, ND = nd;

    // dropped rows: pure zero stores (no loads)
    for (int m = 0; m < ND; m++)
        __stcs(dst + (size_t)droplist[m] * (H / 4), zero4);

    // kept rows: dense branch-free stream; unroll 4 -> 4 loads in flight
#pragma unroll 4
    for (int m = 0; m < NK; m++) {
        size_t off = (size_t)keeplist[m] * (H / 4);
        float4 v = __ldcs(src + off);
        float4 o;
        o.x = c0 ? v.x * 1.5625f : 0.0f;
        o.y = c1 ? v.y * 1.5625f : 0.0f;
        o.z = c2 ? v.z * 1.5625f : 0.0f;
        o.w = c3 ? v.w * 1.5625f : 0.0f;
        __stcs(dst + off, o);
    }
}

// ---------------------------------------------------------------------------
extern "C" void kernel_launch(void* const* d_in, const int* in_sizes, int n_in,
                              void* d_out, int out_size) {
    const float* mu_in    = (const float*)d_in[0];
    const void*  sigma_in = d_in[1];
    const void*  mask     = d_in[2];

    float* mu_out    = (float*)d_out;
    float* sigma_out = (float*)d_out + BH;

    fused_kernel<<<GRID, 512>>>(mu_in, (const unsigned int*)mask, mu_out,
                                (const float4*)sigma_in, (float4*)sigma_out);
}

// round 5
// speedup vs baseline: 1.0453x; 1.0453x over previous
#include <cuda_runtime.h>
#include <cstdint>

// VDPDropout fused single-kernel:
//   mu_out    = keep ? mu*1.25 : 0                       [B, H]
//   Sigma_out = 1.5625 * Sigma * (nz_i & nz_j)           [B, H, H]
// Dropped rows are skipped via PREDICATED loads (@P LDG, no branches), so
// groups of 4 row-loads issue back-to-back (MLP=4) while dropped rows cost
// zero read traffic. Stores are unconditional (output is poisoned).

#define B 32
#define H 2048
#define BH (B * H)              // 65536
#define RPB 16                  // rows per block; 16 | 2048 -> no batch straddle
#define GRID (BH / RPB)         // 4096

// Predicated streaming vec4 load: returns {0,0,0,0} when pred==0, no traffic.
__device__ __forceinline__ float4 ldcs_pred(const float4* p, int pred) {
    float4 v = make_float4(0.f, 0.f, 0.f, 0.f);
    asm volatile(
        "{\n\t.reg .pred p;\n\t"
        "setp.ne.s32 p, %4, 0;\n\t"
        "@p ld.global.cs.v4.f32 {%0,%1,%2,%3}, [%5];\n\t}"
        : "+f"(v.x), "+f"(v.y), "+f"(v.z), "+f"(v.w)
        : "r"(pred), "l"(p));
    return v;
}

__global__ void __launch_bounds__(512)
fused_kernel(const float* __restrict__ mu,
             const unsigned int* __restrict__ mask,
             float* __restrict__ mu_out,
             const float4* __restrict__ Sin,
             float4* __restrict__ Sout) {
    int r0 = blockIdx.x * RPB;          // first row this block owns
    int b  = r0 >> 11;                  // batch index
    __shared__ unsigned char snz[H];

    // ---- mask dtype detection (identical in every block; L2 broadcast) ----
    unsigned int w = (threadIdx.x < 256) ? mask[threadIdx.x] : 0u;
    int bad_i = (threadIdx.x < 256) && (w > 1u);
    int bad_f = (threadIdx.x < 256) && (w != 0u) && (w != 0x3F800000u);
    int any_bad_i = __syncthreads_or(bad_i);
    int any_bad_f = __syncthreads_or(bad_f);
    int kind = !any_bad_i ? 0 : (!any_bad_f ? 1 : 2);

    // ---- recompute this batch's nz row from mu+mask (L2-resident) ----
    int t = threadIdx.x;                // 0..511, 4 elems each = 2048
    float4 mo;
    unsigned char n0, n1, n2, n3;
    {
        float vq[4];
#pragma unroll
        for (int q = 0; q < 4; q++) {
            int gi = b * H + (t << 2) + q;
            bool keep;
            if (kind == 0)      keep = ((const int*)mask)[gi] != 0;
            else if (kind == 1) keep = ((const float*)mask)[gi] != 0.0f;
            else                keep = ((const unsigned char*)mask)[gi] != 0;
            vq[q] = keep ? mu[gi] * 1.25f : 0.0f;
        }
        mo.x = vq[0]; mo.y = vq[1]; mo.z = vq[2]; mo.w = vq[3];
        n0 = vq[0] != 0.0f; n1 = vq[1] != 0.0f;
        n2 = vq[2] != 0.0f; n3 = vq[3] != 0.0f;
    }
    *reinterpret_cast<uchar4*>(snz + (t << 2)) = make_uchar4(n0, n1, n2, n3);

    // one block per batch (the one owning rows [0,16)) also writes mu_out
    if ((r0 & (H - 1)) == 0)
        reinterpret_cast<float4*>(mu_out)[b * (H / 4) + t] = mo;
    __syncthreads();

    int j = t << 2;
    bool c0 = snz[j + 0], c1 = snz[j + 1], c2 = snz[j + 2], c3 = snz[j + 3];

    const float4* src = Sin + (size_t)r0 * (H / 4) + t;
    float4*       dst = Sout + (size_t)r0 * (H / 4) + t;
    int rbase = r0 & (H - 1);

    // ---- Sigma stream: groups of 4 rows, predicated loads batched (MLP=4) ----
#pragma unroll
    for (int g = 0; g < RPB; g += 4) {
        int p0 = snz[rbase + g + 0];
        int p1 = snz[rbase + g + 1];
        int p2 = snz[rbase + g + 2];
        int p3 = snz[rbase + g + 3];
        size_t o0 = (size_t)(g + 0) * (H / 4);
        size_t o1 = (size_t)(g + 1) * (H / 4);
        size_t o2 = (size_t)(g + 2) * (H / 4);
        size_t o3 = (size_t)(g + 3) * (H / 4);

        float4 v0 = ldcs_pred(src + o0, p0);
        float4 v1 = ldcs_pred(src + o1, p1);
        float4 v2 = ldcs_pred(src + o2, p2);
        float4 v3 = ldcs_pred(src + o3, p3);

        // v == 0 for dropped rows, so column predicates suffice.
        float4 w0, w1, w2, w3;
        w0.x = c0 ? v0.x * 1.5625f : 0.f; w0.y = c1 ? v0.y * 1.5625f : 0.f;
        w0.z = c2 ? v0.z * 1.5625f : 0.f; w0.w = c3 ? v0.w * 1.5625f : 0.f;
        w1.x = c0 ? v1.x * 1.5625f : 0.f; w1.y = c1 ? v1.y * 1.5625f : 0.f;
        w1.z = c2 ? v1.z * 1.5625f : 0.f; w1.w = c3 ? v1.w * 1.5625f : 0.f;
        w2.x = c0 ? v2.x * 1.5625f : 0.f; w2.y = c1 ? v2.y * 1.5625f : 0.f;
        w2.z = c2 ? v2.z * 1.5625f : 0.f; w2.w = c3 ? v2.w * 1.5625f : 0.f;
        w3.x = c0 ? v3.x * 1.5625f : 0.f; w3.y = c1 ? v3.y * 1.5625f : 0.f;
        w3.z = c2 ? v3.z * 1.5625f : 0.f; w3.w = c3 ? v3.w * 1.5625f : 0.f;

        __stcs(dst + o0, w0);
        __stcs(dst + o1, w1);
        __stcs(dst + o2, w2);
        __stcs(dst + o3, w3);
    }
}

// ---------------------------------------------------------------------------
extern "C" void kernel_launch(void* const* d_in, const int* in_sizes, int n_in,
                              void* d_out, int out_size) {
    const float* mu_in    = (const float*)d_in[0];
    const void*  sigma_in = d_in[1];
    const void*  mask     = d_in[2];

    float* mu_out    = (float*)d_out;
    float* sigma_out = (float*)d_out + BH;

    fused_kernel<<<GRID, 512>>>(mu_in, (const unsigned int*)mask, mu_out,
                                (const float4*)sigma_in, (float4*)sigma_out);
}